// round 13
// baseline (speedup 1.0000x reference)
#include <cuda_runtime.h>
#include <math.h>

#define DD 512
#define NN 128
#define TB 8

typedef unsigned long long ull;

__device__ float g_picked[NN];

// ---- packed f32x2 helpers (Blackwell FFMA2 path, PTX-only) -----------------
static __device__ __forceinline__ ull ffma2(ull a, ull b, ull c)
{
    ull d;
    asm("fma.rn.f32x2 %0, %1, %2, %3;" : "=l"(d) : "l"(a), "l"(b), "l"(c));
    return d;
}
static __device__ __forceinline__ ull pack2(float x, float y)
{
    ull d;
    asm("mov.b64 %0, {%1, %2};" : "=l"(d) : "f"(x), "f"(y));
    return d;
}
static __device__ __forceinline__ void unpack2(ull v, float& x, float& y)
{
    asm("mov.b64 {%0, %1}, %2;" : "=f"(x), "=f"(y) : "l"(v));
}

// ---------------------------------------------------------------------------
// One CTA (512 threads, 16 warps -> 4 warps/SMSP) per output row k.
// Omega (128x128) register-resident, 2 rows x 16 cols per thread:
//   warp w covers rows [8w, 8w+8); lane: rp = lane>>3 -> rows r0 = 8w+2rp,
//   r0+1; cg = lane&7 -> interleaved col chunks: float4 chunks at cols
//   32q + 4cg (q=0..3). The 8 cg groups of one q read 128 contiguous bytes
//   -> every broadcast LDS.128 is exactly 1 wavefront.
// Per TB=8-site block:
//   phase1: w_b partial dot (4 LDS.128 shared by both rows, 16 ffma2)
//           + 3-stage butterfly (xor 1,2,4) x 2 rows; cg0 -> wfin     [b1]
//   gram:   S[a][b] = p_a . w_b (16 warps x 4 entries)                [b2]
//   LU:     8x8 LU on S by WARP 0 ONLY (publishes L_s, rd_s via smem;
//           lane0 emits probs; __fdividef on serial path)             [b3]
//   fwdsub: y_j in registers (L via scalar broadcast LDS); cg0 -> Y_s [b4]
//   update: Omega[row][c] -= (y_j[row]*rd_j)*y_j[c]  (4 LDS.128/j)
// ---------------------------------------------------------------------------
__global__ void __launch_bounds__(512, 1)
sampler_kernel(const float* __restrict__ P, const int* __restrict__ pos,
               float* __restrict__ out)
{
    __shared__ __align__(16) float pv_s[2][TB][NN];
    __shared__ __align__(16) float wfin[TB][NN];
    __shared__ __align__(16) float Y_s[TB][NN];
    __shared__ __align__(16) float S_s[64];
    __shared__ float L_s[TB][TB];
    __shared__ float rd_s[TB];
    __shared__ unsigned char occ[DD];

    const int k    = blockIdx.x;
    const int tid  = threadIdx.x;
    const int lane = tid & 31;
    const int wid  = tid >> 5;               // 0..15
    const int rp   = lane >> 3;              // 0..3
    const int cg   = lane & 7;               // 0..7
    const int r0   = wid * 8 + rp * 2;       // rows r0, r0+1

    if (tid < DD) occ[tid] = 0;
    __syncthreads();
    if (tid < NN) occ[pos[tid]] = 1;

    const int myPos = pos[k];
    const int xmin  = (k == 0) ? 0 : (pos[k - 1] + 1);
    const int xmax  = DD - NN + k + 1;

    if (tid < DD) out[k * DD + tid] = 0.0f;

    // Omega = I. A2[rr][2q]   covers (row r0+rr, cols 32q+4cg,   +1)
    //            A2[rr][2q+1] covers (row r0+rr, cols 32q+4cg+2, +3)
    ull A2[2][8];
#pragma unroll
    for (int rr = 0; rr < 2; rr++) {
        const int row = r0 + rr;
#pragma unroll
        for (int q = 0; q < 4; q++) {
            const int cb = 32 * q + 4 * cg;
            A2[rr][2 * q]     = pack2((row == cb)     ? 1.0f : 0.0f,
                                      (row == cb + 1) ? 1.0f : 0.0f);
            A2[rr][2 * q + 1] = pack2((row == cb + 2) ? 1.0f : 0.0f,
                                      (row == cb + 3) ? 1.0f : 0.0f);
        }
    }

    // stage first block's 8 P rows: 1024 floats = 256 float4
    if (tid < 256) ((float4*)&pv_s[0][0][0])[tid] = __ldg((const float4*)P + tid);
    __syncthreads();

    float cprod = 1.0f;        // warp 0 only
    int buf = 0;
    for (int i0 = 0; i0 < xmax; i0 += TB) {
        const bool last = (i0 + TB >= xmax);

        float4 pf;
        if (tid < 256 && !last)
            pf = __ldg((const float4*)(P + (i0 + TB) * NN) + tid);

        // ---- phase1: per b, 16-col partial dot for 2 rows + 3-stage butterfly
        float w0[TB], w1[TB];
#pragma unroll
        for (int b = 0; b < TB; b++) {
            const ulonglong2* pb = (const ulonglong2*)&pv_s[buf][b][0];
            ull a00 = 0ull, a01 = 0ull, a10 = 0ull, a11 = 0ull;
#pragma unroll
            for (int q = 0; q < 4; q++) {
                ulonglong2 u = pb[8 * q + cg];    // 1 wavefront per warp
                a00 = ffma2(A2[0][2 * q],     u.x, a00);
                a01 = ffma2(A2[0][2 * q + 1], u.y, a01);
                a10 = ffma2(A2[1][2 * q],     u.x, a10);
                a11 = ffma2(A2[1][2 * q + 1], u.y, a11);
            }
            float x0, y0, x1, y1;
            unpack2(a00, x0, y0); unpack2(a01, x1, y1);
            float s0 = (x0 + y0) + (x1 + y1);
            unpack2(a10, x0, y0); unpack2(a11, x1, y1);
            float s1 = (x0 + y0) + (x1 + y1);
            s0 += __shfl_xor_sync(0xffffffffu, s0, 1);
            s0 += __shfl_xor_sync(0xffffffffu, s0, 2);
            s0 += __shfl_xor_sync(0xffffffffu, s0, 4);
            s1 += __shfl_xor_sync(0xffffffffu, s1, 1);
            s1 += __shfl_xor_sync(0xffffffffu, s1, 2);
            s1 += __shfl_xor_sync(0xffffffffu, s1, 4);
            w0[b] = s0;
            w1[b] = s1;
            if (cg == 0) { wfin[b][r0] = s0; wfin[b][r0 + 1] = s1; }
        }
        if (tid < 256 && !last)
            ((float4*)&pv_s[buf ^ 1][0][0])[tid] = pf;
        __syncthreads();                               // --- b1 ---

        // ---- Gram: 16 warps x 4 entries; S[a][b] = sum_r p_a[r] w_b[r]
        {
            const int e0 = wid * 4;
            float tacc[4];
#pragma unroll
            for (int e = 0; e < 4; e++) {
                int a = (e0 + e) >> 3, b = (e0 + e) & 7;
                float4 pa = ((const float4*)&pv_s[buf][a][0])[lane];
                float4 wb4 = ((const float4*)&wfin[b][0])[lane];
                tacc[e] = pa.x * wb4.x + pa.y * wb4.y + pa.z * wb4.z + pa.w * wb4.w;
            }
#pragma unroll
            for (int off = 16; off; off >>= 1) {
#pragma unroll
                for (int e = 0; e < 4; e++)
                    tacc[e] += __shfl_xor_sync(0xffffffffu, tacc[e], off);
            }
            if (lane == 0)
                *(float4*)&S_s[e0] = make_float4(tacc[0], tacc[1], tacc[2], tacc[3]);
        }
        __syncthreads();                               // --- b2 ---

        // ---- LU on warp 0 only; publish L_s, rd_s; lane0 emits probs
        const int Teff = last ? (xmax - i0) : TB;
        if (wid == 0) {
            float S_row[TB];
#pragma unroll
            for (int b = 0; b < TB; b++)
                S_row[b] = (lane < TB) ? S_s[lane * TB + b] : 0.0f;
            float cp = cprod;
#pragma unroll
            for (int j = 0; j < TB; j++) {
                if (j >= Teff) break;
                float rj[TB];
#pragma unroll
                for (int b = 0; b < TB; b++)
                    rj[b] = __shfl_sync(0xffffffffu, S_row[b], j);
                const float beta = rj[j];
                const int i = i0 + j;
                const bool inwin = (i >= xmin);
                if (lane == 0 && inwin) {
                    float prob = cp * beta;
                    float pcl = (fabsf(prob) > 1e-15f) ? prob : 0.0f;
                    out[k * DD + i] = pcl;
                    if (i == myPos) g_picked[k] = pcl;
                }
                if (inwin) cp *= (1.0f - beta);
                if (i == xmax - 1) break;  // forced last site: no elimination
                const float d  = (!inwin && occ[i]) ? beta : (beta - 1.0f);
                const float rd = __fdividef(1.0f, d);
                const float mult = S_row[j] * rd;   // = L[lane][j] (symmetry)
                if (lane < TB) L_s[lane][j] = mult;
                if (lane == 0) rd_s[j] = rd;
#pragma unroll
                for (int b = 0; b < TB; b++)
                    S_row[b] = fmaf(-mult, rj[b], S_row[b]);
            }
            cprod = cp;
        }
        __syncthreads();                               // --- b3 ---
        if (last) break;

        // ---- forward substitution in registers (y aliases w0/w1):
        //      y_j = w_j - sum_{m<j} L_s[j][m] y_m  (scalar broadcast LDS)
#pragma unroll
        for (int j = 1; j < TB; j++) {
#pragma unroll
            for (int m = 0; m < j; m++) {
                const float ljm = L_s[j][m];
                w0[j] = fmaf(-ljm, w0[m], w0[j]);
                w1[j] = fmaf(-ljm, w1[m], w1[j]);
            }
        }
        if (cg == 0) {
#pragma unroll
            for (int j = 0; j < TB; j++) {
                Y_s[j][r0]     = w0[j];
                Y_s[j][r0 + 1] = w1[j];
            }
        }
        __syncthreads();                               // --- b4 ---

        // ---- rank-8 update: Omega[row][c] -= (y_j[row]*rd_j) * y_j[c]
#pragma unroll
        for (int j = 0; j < TB; j++) {
            const float rdj = rd_s[j];
            const float z0 = -(w0[j] * rdj);
            const float z1 = -(w1[j] * rdj);
            const ull nz0 = pack2(z0, z0);
            const ull nz1 = pack2(z1, z1);
            const ulonglong2* yb = (const ulonglong2*)&Y_s[j][0];
#pragma unroll
            for (int q = 0; q < 4; q++) {
                ulonglong2 u = yb[8 * q + cg];
                A2[0][2 * q]     = ffma2(nz0, u.x, A2[0][2 * q]);
                A2[0][2 * q + 1] = ffma2(nz0, u.y, A2[0][2 * q + 1]);
                A2[1][2 * q]     = ffma2(nz1, u.x, A2[1][2 * q]);
                A2[1][2 * q + 1] = ffma2(nz1, u.y, A2[1][2 * q + 1]);
            }
        }
        buf ^= 1;
    }
}

// ---------------------------------------------------------------------------
// Parallel log-sum of picked probabilities (one warp, tree reduction).
// ---------------------------------------------------------------------------
__global__ void logsum_kernel(float* __restrict__ out_scalar)
{
    int lane = threadIdx.x;
    float s = 0.0f;
    for (int k = lane; k < NN; k += 32) s += logf(g_picked[k]);
#pragma unroll
    for (int o = 16; o; o >>= 1) s += __shfl_xor_sync(0xffffffffu, s, o);
    if (lane == 0) *out_scalar = s;
}

extern "C" void kernel_launch(void* const* d_in, const int* in_sizes, int n_in,
                              void* d_out, int out_size)
{
    const float* P = (const float*)d_in[0];    // [D, N] float32
    const int* pos = (const int*)d_in[1];      // [N] int32, sorted
    float* out = (float*)d_out;                // [N*D probs][1 logprob]

    sampler_kernel<<<NN, 512>>>(P, pos, out);
    logsum_kernel<<<1, 32>>>(out + (out_size - 1));
}